// round 3
// baseline (speedup 1.0000x reference)
#include <cuda_runtime.h>
#include <mma.h>
#include <math.h>
using namespace nvcuda;

#define Sdim 1024
#define Bdim 8
#define Edim 512
#define Hdim 8
#define Ddim 64
#define Ndim 64   // B*H

// ---------------- scratch ----------------
__device__ float g_q[(size_t)Ndim*Sdim*Ddim];        // [n][s][d] 16MB
__device__ float g_k[(size_t)Ndim*Sdim*Ddim];
__device__ float g_v[(size_t)Ndim*Sdim*Ddim];
__device__ float g_bias[(size_t)Sdim*Sdim*Ndim];     // [j][i][n] 256MB
__device__ float g_attn[(size_t)Ndim*Sdim*Sdim];     // [n][i][j] 256MB
__device__ float g_ctx[(size_t)Sdim*Bdim*Edim];      // [m][e] (m = s*8+b)
__device__ float g_x[(size_t)Sdim*Bdim*Edim];

typedef wmma::fragment<wmma::matrix_a,16,16,8,wmma::precision::tf32,wmma::row_major> FragA;
typedef wmma::fragment<wmma::matrix_b,16,16,8,wmma::precision::tf32,wmma::col_major> FragBc;
typedef wmma::fragment<wmma::matrix_b,16,16,8,wmma::precision::tf32,wmma::row_major> FragBr;
typedef wmma::fragment<wmma::accumulator,16,16,8,float> FragC;

template<class F> __device__ __forceinline__ void cvt_tf32(F& f){
    #pragma unroll
    for(int i=0;i<f.num_elements;i++) f.x[i]=wmma::__float_to_tf32(f.x[i]);
}

// =======================================================================
// K1: QKV projection (tf32 TC).  C[m,o] = X[m,:].W[o,:] + b[o]
// out layout q[n=(b*H+h)][s][d];  o-tile of 64 == one head h = blockIdx.y
// =======================================================================
__global__ void __launch_bounds__(256) proj_tc(const float* __restrict__ X,
    const float* __restrict__ W, const float* __restrict__ bias, int sel)
{
    __shared__ float sx[128*72];
    int tid=threadIdx.x, w=tid>>5;
    int m0=blockIdx.x*128, o0=blockIdx.y*64;
    int wy=w&3, wx=w>>2;
    FragC acc[2][2];
    #pragma unroll
    for(int r=0;r<2;r++)
        #pragma unroll
        for(int c=0;c<2;c++) wmma::fill_fragment(acc[r][c],0.f);

    for(int k0=0;k0<Edim;k0+=8){
        FragA a[2]; FragBc b[2];
        #pragma unroll
        for(int r=0;r<2;r++){
            wmma::load_matrix_sync(a[r], X+(size_t)(m0+wy*32+r*16)*Edim+k0, Edim);
            cvt_tf32(a[r]);
        }
        #pragma unroll
        for(int c=0;c<2;c++){
            wmma::load_matrix_sync(b[c], W+(size_t)(o0+wx*32+c*16)*Edim+k0, Edim);
            cvt_tf32(b[c]);
        }
        #pragma unroll
        for(int r=0;r<2;r++)
            #pragma unroll
            for(int c=0;c<2;c++) wmma::mma_sync(acc[r][c],a[r],b[c],acc[r][c]);
    }
    #pragma unroll
    for(int r=0;r<2;r++)
        #pragma unroll
        for(int c=0;c<2;c++)
            wmma::store_matrix_sync(&sx[(wy*32+r*16)*72+wx*32+c*16],acc[r][c],72,wmma::mem_row_major);
    __syncthreads();

    float* out=(sel==0)?g_q:((sel==1)?g_k:g_v);
    int r=tid>>1, half=tid&1;
    int m=m0+r, s=m>>3, bb=m&7, h=blockIdx.y;
    size_t base=((size_t)(bb*Hdim+h)*Sdim+s)*Ddim + half*32;
    #pragma unroll
    for(int u=0;u<8;u++){
        int d=half*32+u*4;
        float4 v=*(float4*)&sx[r*72+d];
        v.x+=bias[o0+d]; v.y+=bias[o0+d+1]; v.z+=bias[o0+d+2]; v.w+=bias[o0+d+3];
        *(float4*)&out[base+u*4]=v;
    }
}

// =======================================================================
// K2: edge-key bias (tf32 TC).  per j: bias[j][i][n] = ek[j][i][:] . q[n][j][:]
// block: i-tile 128, one j.  8 warps x 16 i-rows, n = 64 (4 frags).
// =======================================================================
__global__ void __launch_bounds__(256) biasgemm_tc(const float* __restrict__ ek)
{
    __shared__ float Bs[64*72];     // [n][d], pre-converted tf32
    int tid=threadIdx.x, w=tid>>5;
    int i0=blockIdx.x*128; int j=blockIdx.y;

    for(int idx=tid; idx<4096; idx+=256){
        int n=idx>>6, d=idx&63;
        Bs[n*72+d]=wmma::__float_to_tf32(g_q[(size_t)n*(Sdim*Ddim)+(size_t)j*Ddim+d]);
    }
    __syncthreads();

    FragC acc[4];
    #pragma unroll
    for(int c=0;c<4;c++) wmma::fill_fragment(acc[c],0.f);
    const float* ekp = ek + (size_t)j*(Sdim*Ddim) + (size_t)(i0+w*16)*Ddim;
    #pragma unroll
    for(int kk=0;kk<8;kk++){
        FragA a;
        wmma::load_matrix_sync(a, ekp+kk*8, Ddim); cvt_tf32(a);
        #pragma unroll
        for(int c=0;c<4;c++){
            FragBc b;
            wmma::load_matrix_sync(b, &Bs[(c*16)*72+kk*8], 72);
            wmma::mma_sync(acc[c],a,b,acc[c]);
        }
    }
    #pragma unroll
    for(int c=0;c<4;c++)
        wmma::store_matrix_sync(&g_bias[(size_t)j*(Sdim*Ndim)+(size_t)(i0+w*16)*Ndim+c*16],
                                acc[c], Ndim, wmma::mem_row_major);
}

// =======================================================================
// K3: raw QK scores (tf32 TC).  g_attn[n][i][j] = q[n,i,:].k[n,j,:]
// block tile 64i x 64j, 8 warps (4 i-strips x 2 j-halves, warp = 16x32)
// =======================================================================
__global__ void __launch_bounds__(256) score_tc()
{
    int tid=threadIdx.x, w=tid>>5;
    int i0=blockIdx.x*64, j0=blockIdx.y*64, n=blockIdx.z;
    int wy=w&3, wx=w>>2;
    const float* qp = g_q + (size_t)n*(Sdim*Ddim) + (size_t)(i0+wy*16)*Ddim;
    const float* kp = g_k + (size_t)n*(Sdim*Ddim) + (size_t)(j0+wx*32)*Ddim;
    FragC acc[2];
    wmma::fill_fragment(acc[0],0.f); wmma::fill_fragment(acc[1],0.f);
    #pragma unroll
    for(int kk=0;kk<8;kk++){
        FragA a; wmma::load_matrix_sync(a, qp+kk*8, Ddim); cvt_tf32(a);
        #pragma unroll
        for(int c=0;c<2;c++){
            FragBc b; wmma::load_matrix_sync(b, kp+(size_t)(c*16)*Ddim+kk*8, Ddim); cvt_tf32(b);
            wmma::mma_sync(acc[c],a,b,acc[c]);
        }
    }
    #pragma unroll
    for(int c=0;c<2;c++)
        wmma::store_matrix_sync(&g_attn[(size_t)n*(Sdim*Sdim)+(size_t)(i0+wy*16)*Sdim+j0+wx*32+c*16],
                                acc[c], Sdim, wmma::mem_row_major);
}

// =======================================================================
// K4: fused bias + scale + mask + softmax.
// block: (i fixed, 8 consecutive n).  bias read is sector-coalesced.
// =======================================================================
__global__ void __launch_bounds__(256) softmax_fused(const int* __restrict__ mask)
{
    __shared__ float bias_s[8*1028];
    __shared__ float red[8];
    int tid=threadIdx.x, lane=tid&31, w=tid>>5;
    int i=blockIdx.x, n0=blockIdx.y*8;

    for(int idx=tid; idx<8192; idx+=256){
        int j=idx>>3, nn=idx&7;
        bias_s[nn*1028+j]=g_bias[(size_t)j*(Sdim*Ndim)+(size_t)i*Ndim+n0+nn];
    }
    __syncthreads();

    for(int nn=0;nn<8;nn++){
        int n=n0+nn;
        size_t ro=(size_t)n*(Sdim*Sdim)+(size_t)i*Sdim;
        float4 qk=*(float4*)&g_attn[ro+tid*4];
        int4 mv=*(const int4*)&mask[ro+tid*4];
        const float* bp=&bias_s[nn*1028+tid*4];
        float v0 = mv.x ? -1e30f : (qk.x+bp[0])*0.125f;
        float v1 = mv.y ? -1e30f : (qk.y+bp[1])*0.125f;
        float v2 = mv.z ? -1e30f : (qk.z+bp[2])*0.125f;
        float v3 = mv.w ? -1e30f : (qk.w+bp[3])*0.125f;

        float mx=fmaxf(fmaxf(v0,v1),fmaxf(v2,v3));
        #pragma unroll
        for(int o=16;o;o>>=1) mx=fmaxf(mx,__shfl_xor_sync(0xffffffffu,mx,o));
        if(lane==0) red[w]=mx;
        __syncthreads();
        mx=red[0];
        #pragma unroll
        for(int r=1;r<8;r++) mx=fmaxf(mx,red[r]);
        __syncthreads();

        v0=__expf(v0-mx); v1=__expf(v1-mx); v2=__expf(v2-mx); v3=__expf(v3-mx);
        float sm=v0+v1+v2+v3;
        #pragma unroll
        for(int o=16;o;o>>=1) sm+=__shfl_xor_sync(0xffffffffu,sm,o);
        if(lane==0) red[w]=sm;
        __syncthreads();
        sm=red[0];
        #pragma unroll
        for(int r=1;r<8;r++) sm+=red[r];
        __syncthreads();

        float inv=1.0f/sm;
        float4 o4=make_float4(v0*inv,v1*inv,v2*inv,v3*inv);
        *(float4*)&g_attn[ro+tid*4]=o4;
    }
}

// =======================================================================
// K5a: PV (tf32 TC).  ctx[i][n*64+d] = sum_j attn[n,i,j]*v[n,j,d]
// block: 128 i-rows, one n.  8 warps x 16 i-rows, d=64 (4 frags).
// =======================================================================
__global__ void __launch_bounds__(256) pv_tc()
{
    __shared__ float vs[64*72];
    int tid=threadIdx.x, w=tid>>5;
    int i0=blockIdx.x*128; int n=blockIdx.y;
    FragC acc[4];
    #pragma unroll
    for(int c=0;c<4;c++) wmma::fill_fragment(acc[c],0.f);
    const float* ap = g_attn + (size_t)n*(Sdim*Sdim) + (size_t)(i0+w*16)*Sdim;

    for(int k0=0;k0<Sdim;k0+=64){
        for(int idx=tid; idx<4096; idx+=256){
            int jj=idx>>6, d=idx&63;
            vs[jj*72+d]=wmma::__float_to_tf32(g_v[(size_t)n*(Sdim*Ddim)+(size_t)(k0+jj)*Ddim+d]);
        }
        __syncthreads();
        #pragma unroll
        for(int kk=0;kk<8;kk++){
            FragA a; wmma::load_matrix_sync(a, ap+k0+kk*8, Sdim); cvt_tf32(a);
            #pragma unroll
            for(int c=0;c<4;c++){
                FragBr b; wmma::load_matrix_sync(b, &vs[(kk*8)*72+c*16], 72);
                wmma::mma_sync(acc[c],a,b,acc[c]);
            }
        }
        __syncthreads();
    }
    #pragma unroll
    for(int c=0;c<4;c++)
        wmma::store_matrix_sync(&g_ctx[(size_t)(i0+w*16)*(Bdim*Edim)+(size_t)n*Ddim+c*16],
                                acc[c], Bdim*Edim, wmma::mem_row_major);
}

// =======================================================================
// K5b: edge-value (tf32 TC).  per i: ctx[i][n*64+d] += attn[:,i,:]@ev[i]
// block = one i, 4 warps x 16 n-rows, K=1024 loop.
// =======================================================================
__global__ void __launch_bounds__(128) ev_tc(const float* __restrict__ ev)
{
    __shared__ float es[64*72];
    int tid=threadIdx.x, w=tid>>5;   // 0..3
    int i=blockIdx.x;
    FragC acc[4];
    #pragma unroll
    for(int c=0;c<4;c++)
        wmma::load_matrix_sync(acc[c],
            &g_ctx[(size_t)i*(Bdim*Edim)+(size_t)(w*16)*Ddim+c*16], Ddim, wmma::mem_row_major);

    for(int k0=0;k0<Sdim;k0+=64){
        for(int idx=tid; idx<4096; idx+=128){
            int jj=idx>>6, d=idx&63;
            es[jj*72+d]=wmma::__float_to_tf32(ev[(size_t)i*(Sdim*Ddim)+(size_t)(k0+jj)*Ddim+d]);
        }
        __syncthreads();
        const float* ap = g_attn + (size_t)(w*16)*(Sdim*Sdim) + (size_t)i*Sdim + k0;
        #pragma unroll
        for(int kk=0;kk<8;kk++){
            FragA a; wmma::load_matrix_sync(a, ap+kk*8, Sdim*Sdim); cvt_tf32(a);
            #pragma unroll
            for(int c=0;c<4;c++){
                FragBr b; wmma::load_matrix_sync(b, &es[(kk*8)*72+c*16], 72);
                wmma::mma_sync(acc[c],a,b,acc[c]);
            }
        }
        __syncthreads();
    }
    #pragma unroll
    for(int c=0;c<4;c++)
        wmma::store_matrix_sync(&g_ctx[(size_t)i*(Bdim*Edim)+(size_t)(w*16)*Ddim+c*16],
                                acc[c], Ddim, wmma::mem_row_major);
}

// =======================================================================
// K6: output projection + residual (tf32 TC) -> g_x
// =======================================================================
__global__ void __launch_bounds__(256) outproj_tc(const float* __restrict__ W,
    const float* __restrict__ bias, const float* __restrict__ resid)
{
    __shared__ float sx[128*72];
    int tid=threadIdx.x, w=tid>>5;
    int m0=blockIdx.x*128, o0=blockIdx.y*64;
    int wy=w&3, wx=w>>2;
    FragC acc[2][2];
    #pragma unroll
    for(int r=0;r<2;r++)
        #pragma unroll
        for(int c=0;c<2;c++) wmma::fill_fragment(acc[r][c],0.f);

    for(int k0=0;k0<Edim;k0+=8){
        FragA a[2]; FragBc b[2];
        #pragma unroll
        for(int r=0;r<2;r++){
            wmma::load_matrix_sync(a[r], g_ctx+(size_t)(m0+wy*32+r*16)*Edim+k0, Edim);
            cvt_tf32(a[r]);
        }
        #pragma unroll
        for(int c=0;c<2;c++){
            wmma::load_matrix_sync(b[c], W+(size_t)(o0+wx*32+c*16)*Edim+k0, Edim);
            cvt_tf32(b[c]);
        }
        #pragma unroll
        for(int r=0;r<2;r++)
            #pragma unroll
            for(int c=0;c<2;c++) wmma::mma_sync(acc[r][c],a[r],b[c],acc[r][c]);
    }
    #pragma unroll
    for(int r=0;r<2;r++)
        #pragma unroll
        for(int c=0;c<2;c++)
            wmma::store_matrix_sync(&sx[(wy*32+r*16)*72+wx*32+c*16],acc[r][c],72,wmma::mem_row_major);
    __syncthreads();

    int r=tid>>1, half=tid&1;
    int m=m0+r;
    size_t base=(size_t)m*Edim + o0 + half*32;
    #pragma unroll
    for(int u=0;u<8;u++){
        int d=half*32+u*4;
        float4 v=*(float4*)&sx[r*72+d];
        float4 rs=*(const float4*)&resid[base+u*4];
        v.x+=bias[o0+d]  +rs.x; v.y+=bias[o0+d+1]+rs.y;
        v.z+=bias[o0+d+2]+rs.z; v.w+=bias[o0+d+3]+rs.w;
        *(float4*)&g_x[base+u*4]=v;
    }
}

// =======================================================================
// K7: LayerNorm over last dim (512)
// =======================================================================
__global__ void __launch_bounds__(256) ln_kernel(const float* __restrict__ gamma,
     const float* __restrict__ beta, float* __restrict__ out)
{
    int m = blockIdx.x, tid = threadIdx.x;
    float a = g_x[(size_t)m*Edim + tid];
    float b = g_x[(size_t)m*Edim + 256 + tid];
    __shared__ float s1[256], s2[256];
    s1[tid] = a+b; s2[tid] = a*a + b*b;
    __syncthreads();
    for (int s=128;s>0;s>>=1){
        if(tid<s){ s1[tid]+=s1[tid+s]; s2[tid]+=s2[tid+s]; }
        __syncthreads();
    }
    float mean = s1[0] * (1.0f/512.0f);
    float var  = s2[0] * (1.0f/512.0f) - mean*mean;
    float rstd = rsqrtf(var + 1e-5f);
    out[(size_t)m*Edim + tid]       = gamma[tid]*(a-mean)*rstd + beta[tid];
    out[(size_t)m*Edim + 256 + tid] = gamma[256+tid]*(b-mean)*rstd + beta[256+tid];
}

// =======================================================================
extern "C" void kernel_launch(void* const* d_in, const int* in_sizes, int n_in,
                              void* d_out, int out_size)
{
    const float* query      = (const float*)d_in[0];
    const float* key        = (const float*)d_in[1];
    const float* value      = (const float*)d_in[2];
    const float* edge_key   = (const float*)d_in[3];
    const float* edge_value = (const float*)d_in[4];
    const int*   mask       = (const int*)  d_in[5];
    int base = (n_in == 17) ? 7 : 6;
    const float* Wq = (const float*)d_in[base+0];
    const float* bq = (const float*)d_in[base+1];
    const float* Wk = (const float*)d_in[base+2];
    const float* bk = (const float*)d_in[base+3];
    const float* Wv = (const float*)d_in[base+4];
    const float* bv = (const float*)d_in[base+5];
    const float* Wo = (const float*)d_in[base+6];
    const float* bo = (const float*)d_in[base+7];
    const float* gamma = (const float*)d_in[base+8];
    const float* beta  = (const float*)d_in[base+9];

    proj_tc<<<dim3(64,8),256>>>(query, Wq, bq, 0);
    proj_tc<<<dim3(64,8),256>>>(key,   Wk, bk, 1);
    proj_tc<<<dim3(64,8),256>>>(value, Wv, bv, 2);
    biasgemm_tc<<<dim3(8,1024),256>>>(edge_key);
    score_tc<<<dim3(16,16,64),256>>>();
    softmax_fused<<<dim3(1024,8),256>>>(mask);
    pv_tc<<<dim3(8,64),256>>>();
    ev_tc<<<1024,128>>>(edge_value);
    outproj_tc<<<dim3(64,8),256>>>(Wo, bo, query);
    ln_kernel<<<dim3(8192),256>>>(gamma, beta, (float*)d_out);
}

// round 4
// speedup vs baseline: 1.0006x; 1.0006x over previous
#include <cuda_runtime.h>
#include <mma.h>
#include <math.h>
using namespace nvcuda;

#define Sdim 1024
#define Bdim 8
#define Edim 512
#define Hdim 8
#define Ddim 64
#define Ndim 64   // B*H

// ---------------- scratch ----------------
__device__ float g_q[(size_t)Ndim*Sdim*Ddim];        // [n][s][d] 16MB
__device__ float g_k[(size_t)Ndim*Sdim*Ddim];
__device__ float g_v[(size_t)Ndim*Sdim*Ddim];
__device__ float g_bias[(size_t)Sdim*Sdim*Ndim];     // [j][i][n] 256MB
__device__ float g_attn[(size_t)Ndim*Sdim*Sdim];     // [n][i][j] 256MB
__device__ float g_ctx[(size_t)Sdim*Bdim*Edim];      // [m][e] (m = s*8+b)
__device__ float g_x[(size_t)Sdim*Bdim*Edim];

typedef wmma::fragment<wmma::matrix_a,16,16,8,wmma::precision::tf32,wmma::row_major> FragA;
typedef wmma::fragment<wmma::matrix_b,16,16,8,wmma::precision::tf32,wmma::col_major> FragBc;
typedef wmma::fragment<wmma::matrix_b,16,16,8,wmma::precision::tf32,wmma::row_major> FragBr;
typedef wmma::fragment<wmma::accumulator,16,16,8,float> FragC;

template<class F> __device__ __forceinline__ void cvt_tf32(F& f){
    #pragma unroll
    for(int i=0;i<f.num_elements;i++) f.x[i]=wmma::__float_to_tf32(f.x[i]);
}

// =======================================================================
// K1: QKV projection (tf32 TC).  C[m,o] = X[m,:].W[o,:] + b[o]
// out layout q[n=(b*H+h)][s][d];  o-tile of 64 == one head h = blockIdx.y
// =======================================================================
__global__ void __launch_bounds__(256) proj_tc(const float* __restrict__ X,
    const float* __restrict__ W, const float* __restrict__ bias, int sel)
{
    __shared__ float sx[128*72];
    int tid=threadIdx.x, w=tid>>5;
    int m0=blockIdx.x*128, o0=blockIdx.y*64;
    int wy=w&3, wx=w>>2;
    FragC acc[2][2];
    #pragma unroll
    for(int r=0;r<2;r++)
        #pragma unroll
        for(int c=0;c<2;c++) wmma::fill_fragment(acc[r][c],0.f);

    for(int k0=0;k0<Edim;k0+=8){
        FragA a[2]; FragBc b[2];
        #pragma unroll
        for(int r=0;r<2;r++){
            wmma::load_matrix_sync(a[r], X+(size_t)(m0+wy*32+r*16)*Edim+k0, Edim);
            cvt_tf32(a[r]);
        }
        #pragma unroll
        for(int c=0;c<2;c++){
            wmma::load_matrix_sync(b[c], W+(size_t)(o0+wx*32+c*16)*Edim+k0, Edim);
            cvt_tf32(b[c]);
        }
        #pragma unroll
        for(int r=0;r<2;r++)
            #pragma unroll
            for(int c=0;c<2;c++) wmma::mma_sync(acc[r][c],a[r],b[c],acc[r][c]);
    }
    #pragma unroll
    for(int r=0;r<2;r++)
        #pragma unroll
        for(int c=0;c<2;c++)
            wmma::store_matrix_sync(&sx[(wy*32+r*16)*72+wx*32+c*16],acc[r][c],72,wmma::mem_row_major);
    __syncthreads();

    float* out=(sel==0)?g_q:((sel==1)?g_k:g_v);
    int r=tid>>1, half=tid&1;
    int m=m0+r, s=m>>3, bb=m&7, h=blockIdx.y;
    size_t base=((size_t)(bb*Hdim+h)*Sdim+s)*Ddim + half*32;
    #pragma unroll
    for(int u=0;u<8;u++){
        int d=half*32+u*4;
        float4 v=*(float4*)&sx[r*72+d];
        v.x+=bias[o0+d]; v.y+=bias[o0+d+1]; v.z+=bias[o0+d+2]; v.w+=bias[o0+d+3];
        *(float4*)&out[base+u*4]=v;
    }
}

// =======================================================================
// K2: edge-key bias (tf32 TC).  per j: bias[j][i][n] = ek[j][i][:] . q[n][j][:]
// block: i-tile 128, one j.  8 warps x 16 i-rows, n = 64 (4 frags).
// =======================================================================
__global__ void __launch_bounds__(256) biasgemm_tc(const float* __restrict__ ek)
{
    __shared__ float Bs[64*72];     // [n][d], pre-converted tf32
    int tid=threadIdx.x, w=tid>>5;
    int i0=blockIdx.x*128; int j=blockIdx.y;

    for(int idx=tid; idx<4096; idx+=256){
        int n=idx>>6, d=idx&63;
        Bs[n*72+d]=wmma::__float_to_tf32(g_q[(size_t)n*(Sdim*Ddim)+(size_t)j*Ddim+d]);
    }
    __syncthreads();

    FragC acc[4];
    #pragma unroll
    for(int c=0;c<4;c++) wmma::fill_fragment(acc[c],0.f);
    const float* ekp = ek + (size_t)j*(Sdim*Ddim) + (size_t)(i0+w*16)*Ddim;
    #pragma unroll
    for(int kk=0;kk<8;kk++){
        FragA a;
        wmma::load_matrix_sync(a, ekp+kk*8, Ddim); cvt_tf32(a);
        #pragma unroll
        for(int c=0;c<4;c++){
            FragBc b;
            wmma::load_matrix_sync(b, &Bs[(c*16)*72+kk*8], 72);
            wmma::mma_sync(acc[c],a,b,acc[c]);
        }
    }
    #pragma unroll
    for(int c=0;c<4;c++)
        wmma::store_matrix_sync(&g_bias[(size_t)j*(Sdim*Ndim)+(size_t)(i0+w*16)*Ndim+c*16],
                                acc[c], Ndim, wmma::mem_row_major);
}

// =======================================================================
// K3: raw QK scores (tf32 TC).  g_attn[n][i][j] = q[n,i,:].k[n,j,:]
// block tile 64i x 64j, 8 warps (4 i-strips x 2 j-halves, warp = 16x32)
// =======================================================================
__global__ void __launch_bounds__(256) score_tc()
{
    int tid=threadIdx.x, w=tid>>5;
    int i0=blockIdx.x*64, j0=blockIdx.y*64, n=blockIdx.z;
    int wy=w&3, wx=w>>2;
    const float* qp = g_q + (size_t)n*(Sdim*Ddim) + (size_t)(i0+wy*16)*Ddim;
    const float* kp = g_k + (size_t)n*(Sdim*Ddim) + (size_t)(j0+wx*32)*Ddim;
    FragC acc[2];
    wmma::fill_fragment(acc[0],0.f); wmma::fill_fragment(acc[1],0.f);
    #pragma unroll
    for(int kk=0;kk<8;kk++){
        FragA a; wmma::load_matrix_sync(a, qp+kk*8, Ddim); cvt_tf32(a);
        #pragma unroll
        for(int c=0;c<2;c++){
            FragBc b; wmma::load_matrix_sync(b, kp+(size_t)(c*16)*Ddim+kk*8, Ddim); cvt_tf32(b);
            wmma::mma_sync(acc[c],a,b,acc[c]);
        }
    }
    #pragma unroll
    for(int c=0;c<2;c++)
        wmma::store_matrix_sync(&g_attn[(size_t)n*(Sdim*Sdim)+(size_t)(i0+wy*16)*Sdim+j0+wx*32+c*16],
                                acc[c], Sdim, wmma::mem_row_major);
}

// =======================================================================
// K4: fused bias + scale + mask + softmax.
// block: (i fixed, 8 consecutive n).  bias read is sector-coalesced.
// =======================================================================
__global__ void __launch_bounds__(256) softmax_fused(const int* __restrict__ mask)
{
    __shared__ float bias_s[8*1028];
    __shared__ float red[8];
    int tid=threadIdx.x, lane=tid&31, w=tid>>5;
    int i=blockIdx.x, n0=blockIdx.y*8;

    for(int idx=tid; idx<8192; idx+=256){
        int j=idx>>3, nn=idx&7;
        bias_s[nn*1028+j]=g_bias[(size_t)j*(Sdim*Ndim)+(size_t)i*Ndim+n0+nn];
    }
    __syncthreads();

    for(int nn=0;nn<8;nn++){
        int n=n0+nn;
        size_t ro=(size_t)n*(Sdim*Sdim)+(size_t)i*Sdim;
        float4 qk=*(float4*)&g_attn[ro+tid*4];
        int4 mv=*(const int4*)&mask[ro+tid*4];
        const float* bp=&bias_s[nn*1028+tid*4];
        float v0 = mv.x ? -1e30f : (qk.x+bp[0])*0.125f;
        float v1 = mv.y ? -1e30f : (qk.y+bp[1])*0.125f;
        float v2 = mv.z ? -1e30f : (qk.z+bp[2])*0.125f;
        float v3 = mv.w ? -1e30f : (qk.w+bp[3])*0.125f;

        float mx=fmaxf(fmaxf(v0,v1),fmaxf(v2,v3));
        #pragma unroll
        for(int o=16;o;o>>=1) mx=fmaxf(mx,__shfl_xor_sync(0xffffffffu,mx,o));
        if(lane==0) red[w]=mx;
        __syncthreads();
        mx=red[0];
        #pragma unroll
        for(int r=1;r<8;r++) mx=fmaxf(mx,red[r]);
        __syncthreads();

        v0=__expf(v0-mx); v1=__expf(v1-mx); v2=__expf(v2-mx); v3=__expf(v3-mx);
        float sm=v0+v1+v2+v3;
        #pragma unroll
        for(int o=16;o;o>>=1) sm+=__shfl_xor_sync(0xffffffffu,sm,o);
        if(lane==0) red[w]=sm;
        __syncthreads();
        sm=red[0];
        #pragma unroll
        for(int r=1;r<8;r++) sm+=red[r];
        __syncthreads();

        float inv=1.0f/sm;
        float4 o4=make_float4(v0*inv,v1*inv,v2*inv,v3*inv);
        *(float4*)&g_attn[ro+tid*4]=o4;
    }
}

// =======================================================================
// K5a: PV (tf32 TC).  ctx[i][n*64+d] = sum_j attn[n,i,j]*v[n,j,d]
// block: 128 i-rows, one n.  8 warps x 16 i-rows, d=64 (4 frags).
// =======================================================================
__global__ void __launch_bounds__(256) pv_tc()
{
    __shared__ float vs[64*72];
    int tid=threadIdx.x, w=tid>>5;
    int i0=blockIdx.x*128; int n=blockIdx.y;
    FragC acc[4];
    #pragma unroll
    for(int c=0;c<4;c++) wmma::fill_fragment(acc[c],0.f);
    const float* ap = g_attn + (size_t)n*(Sdim*Sdim) + (size_t)(i0+w*16)*Sdim;

    for(int k0=0;k0<Sdim;k0+=64){
        for(int idx=tid; idx<4096; idx+=256){
            int jj=idx>>6, d=idx&63;
            vs[jj*72+d]=wmma::__float_to_tf32(g_v[(size_t)n*(Sdim*Ddim)+(size_t)(k0+jj)*Ddim+d]);
        }
        __syncthreads();
        #pragma unroll
        for(int kk=0;kk<8;kk++){
            FragA a; wmma::load_matrix_sync(a, ap+k0+kk*8, Sdim); cvt_tf32(a);
            #pragma unroll
            for(int c=0;c<4;c++){
                FragBr b; wmma::load_matrix_sync(b, &vs[(kk*8)*72+c*16], 72);
                wmma::mma_sync(acc[c],a,b,acc[c]);
            }
        }
        __syncthreads();
    }
    #pragma unroll
    for(int c=0;c<4;c++)
        wmma::store_matrix_sync(&g_ctx[(size_t)(i0+w*16)*(Bdim*Edim)+(size_t)n*Ddim+c*16],
                                acc[c], Bdim*Edim, wmma::mem_row_major);
}

// =======================================================================
// K5b: edge-value (tf32 TC).  per i: ctx[i][n*64+d] += attn[:,i,:]@ev[i]
// block = one i, 4 warps x 16 n-rows, K=1024 loop.
// =======================================================================
__global__ void __launch_bounds__(128) ev_tc(const float* __restrict__ ev)
{
    __shared__ float es[64*72];
    int tid=threadIdx.x, w=tid>>5;   // 0..3
    int i=blockIdx.x;
    FragC acc[4];
    #pragma unroll
    for(int c=0;c<4;c++)
        wmma::load_matrix_sync(acc[c],
            &g_ctx[(size_t)i*(Bdim*Edim)+(size_t)(w*16)*Ddim+c*16], Ddim, wmma::mem_row_major);

    for(int k0=0;k0<Sdim;k0+=64){
        for(int idx=tid; idx<4096; idx+=128){
            int jj=idx>>6, d=idx&63;
            es[jj*72+d]=wmma::__float_to_tf32(ev[(size_t)i*(Sdim*Ddim)+(size_t)(k0+jj)*Ddim+d]);
        }
        __syncthreads();
        const float* ap = g_attn + (size_t)(w*16)*(Sdim*Sdim) + (size_t)i*Sdim + k0;
        #pragma unroll
        for(int kk=0;kk<8;kk++){
            FragA a; wmma::load_matrix_sync(a, ap+kk*8, Sdim*Sdim); cvt_tf32(a);
            #pragma unroll
            for(int c=0;c<4;c++){
                FragBr b; wmma::load_matrix_sync(b, &es[(kk*8)*72+c*16], 72);
                wmma::mma_sync(acc[c],a,b,acc[c]);
            }
        }
        __syncthreads();
    }
    #pragma unroll
    for(int c=0;c<4;c++)
        wmma::store_matrix_sync(&g_ctx[(size_t)i*(Bdim*Edim)+(size_t)(w*16)*Ddim+c*16],
                                acc[c], Ddim, wmma::mem_row_major);
}

// =======================================================================
// K6: output projection + residual (tf32 TC) -> g_x
// =======================================================================
__global__ void __launch_bounds__(256) outproj_tc(const float* __restrict__ W,
    const float* __restrict__ bias, const float* __restrict__ resid)
{
    __shared__ float sx[128*72];
    int tid=threadIdx.x, w=tid>>5;
    int m0=blockIdx.x*128, o0=blockIdx.y*64;
    int wy=w&3, wx=w>>2;
    FragC acc[2][2];
    #pragma unroll
    for(int r=0;r<2;r++)
        #pragma unroll
        for(int c=0;c<2;c++) wmma::fill_fragment(acc[r][c],0.f);

    for(int k0=0;k0<Edim;k0+=8){
        FragA a[2]; FragBc b[2];
        #pragma unroll
        for(int r=0;r<2;r++){
            wmma::load_matrix_sync(a[r], g_ctx+(size_t)(m0+wy*32+r*16)*Edim+k0, Edim);
            cvt_tf32(a[r]);
        }
        #pragma unroll
        for(int c=0;c<2;c++){
            wmma::load_matrix_sync(b[c], W+(size_t)(o0+wx*32+c*16)*Edim+k0, Edim);
            cvt_tf32(b[c]);
        }
        #pragma unroll
        for(int r=0;r<2;r++)
            #pragma unroll
            for(int c=0;c<2;c++) wmma::mma_sync(acc[r][c],a[r],b[c],acc[r][c]);
    }
    #pragma unroll
    for(int r=0;r<2;r++)
        #pragma unroll
        for(int c=0;c<2;c++)
            wmma::store_matrix_sync(&sx[(wy*32+r*16)*72+wx*32+c*16],acc[r][c],72,wmma::mem_row_major);
    __syncthreads();

    int r=tid>>1, half=tid&1;
    int m=m0+r;
    size_t base=(size_t)m*Edim + o0 + half*32;
    #pragma unroll
    for(int u=0;u<8;u++){
        int d=half*32+u*4;
        float4 v=*(float4*)&sx[r*72+d];
        float4 rs=*(const float4*)&resid[base+u*4];
        v.x+=bias[o0+d]  +rs.x; v.y+=bias[o0+d+1]+rs.y;
        v.z+=bias[o0+d+2]+rs.z; v.w+=bias[o0+d+3]+rs.w;
        *(float4*)&g_x[base+u*4]=v;
    }
}

// =======================================================================
// K7: LayerNorm over last dim (512)
// =======================================================================
__global__ void __launch_bounds__(256) ln_kernel(const float* __restrict__ gamma,
     const float* __restrict__ beta, float* __restrict__ out)
{
    int m = blockIdx.x, tid = threadIdx.x;
    float a = g_x[(size_t)m*Edim + tid];
    float b = g_x[(size_t)m*Edim + 256 + tid];
    __shared__ float s1[256], s2[256];
    s1[tid] = a+b; s2[tid] = a*a + b*b;
    __syncthreads();
    for (int s=128;s>0;s>>=1){
        if(tid<s){ s1[tid]+=s1[tid+s]; s2[tid]+=s2[tid+s]; }
        __syncthreads();
    }
    float mean = s1[0] * (1.0f/512.0f);
    float var  = s2[0] * (1.0f/512.0f) - mean*mean;
    float rstd = rsqrtf(var + 1e-5f);
    out[(size_t)m*Edim + tid]       = gamma[tid]*(a-mean)*rstd + beta[tid];
    out[(size_t)m*Edim + 256 + tid] = gamma[256+tid]*(b-mean)*rstd + beta[256+tid];
}

// =======================================================================
extern "C" void kernel_launch(void* const* d_in, const int* in_sizes, int n_in,
                              void* d_out, int out_size)
{
    const float* query      = (const float*)d_in[0];
    const float* key        = (const float*)d_in[1];
    const float* value      = (const float*)d_in[2];
    const float* edge_key   = (const float*)d_in[3];
    const float* edge_value = (const float*)d_in[4];
    const int*   mask       = (const int*)  d_in[5];
    int base = (n_in == 17) ? 7 : 6;
    const float* Wq = (const float*)d_in[base+0];
    const float* bq = (const float*)d_in[base+1];
    const float* Wk = (const float*)d_in[base+2];
    const float* bk = (const float*)d_in[base+3];
    const float* Wv = (const float*)d_in[base+4];
    const float* bv = (const float*)d_in[base+5];
    const float* Wo = (const float*)d_in[base+6];
    const float* bo = (const float*)d_in[base+7];
    const float* gamma = (const float*)d_in[base+8];
    const float* beta  = (const float*)d_in[base+9];

    proj_tc<<<dim3(64,8),256>>>(query, Wq, bq, 0);
    proj_tc<<<dim3(64,8),256>>>(key,   Wk, bk, 1);
    proj_tc<<<dim3(64,8),256>>>(value, Wv, bv, 2);
    biasgemm_tc<<<dim3(8,1024),256>>>(edge_key);
    score_tc<<<dim3(16,16,64),256>>>();
    softmax_fused<<<dim3(1024,8),256>>>(mask);
    pv_tc<<<dim3(8,64),256>>>();
    ev_tc<<<1024,128>>>(edge_value);
    outproj_tc<<<dim3(64,8),256>>>(Wo, bo, query);
    ln_kernel<<<dim3(8192),256>>>(gamma, beta, (float*)d_out);
}